// round 1
// baseline (speedup 1.0000x reference)
#include <cuda_runtime.h>

// Problem constants
#define NTOK   4096          // B*S tokens
#define DM     1024          // model dim
#define HID    4096          // expert hidden
#define NEXP   8
#define TOPK   2
#define NPAIRS (NTOK*TOPK)   // 8192

// ---------------- scratch (allocation-free __device__ globals) ----------------
__device__ float g_h[(size_t)NPAIRS * HID];   // hidden activations per pair (134MB)
__device__ float g_y[(size_t)NPAIRS * DM];    // expert outputs per pair (33.5MB)
__device__ int   g_tok_e[NPAIRS];             // per (token,k): expert id
__device__ float g_tok_w[NPAIRS];             // per (token,k): gate weight
__device__ int   g_tok_slot[NPAIRS];          // per (token,k): slot in compacted pair list
__device__ int   g_pair_tok[NPAIRS];          // per slot: token id
__device__ int   g_cnt[NEXP];
__device__ int   g_off[NEXP];
__device__ int   g_cur[NEXP];

// ---------------- tiny kernels ----------------
__global__ void k_zero() {
    int i = threadIdx.x;
    if (i < NEXP) { g_cnt[i] = 0; }
}

// one warp per token: logits -> softmax -> top-2
__global__ void k_router(const float* __restrict__ x, const float* __restrict__ gw) {
    int gwarp = (blockIdx.x * blockDim.x + threadIdx.x) >> 5;
    int lane  = threadIdx.x & 31;
    if (gwarp >= NTOK) return;
    const float* xr = x + (size_t)gwarp * DM;

    float logit[NEXP];
    #pragma unroll
    for (int e = 0; e < NEXP; e++) {
        const float* wr = gw + e * DM;
        float s = 0.f;
        for (int i = lane; i < DM; i += 32) s += xr[i] * wr[i];
        #pragma unroll
        for (int o = 16; o; o >>= 1) s += __shfl_xor_sync(0xffffffffu, s, o);
        logit[e] = s;
    }
    if (lane == 0) {
        float mx = logit[0];
        #pragma unroll
        for (int e = 1; e < NEXP; e++) mx = fmaxf(mx, logit[e]);
        float p[NEXP], den = 0.f;
        #pragma unroll
        for (int e = 0; e < NEXP; e++) { p[e] = expf(logit[e] - mx); den += p[e]; }
        float inv = 1.f / den;

        // top-1 (ties -> lowest index, matches jax.lax.top_k)
        int m0 = 0;
        #pragma unroll
        for (int e = 1; e < NEXP; e++) if (p[e] > p[m0]) m0 = e;
        // top-2 (excluding m0)
        int m1 = (m0 == 0) ? 1 : 0;
        #pragma unroll
        for (int e = 0; e < NEXP; e++) if (e != m0 && p[e] > p[m1]) m1 = e;

        g_tok_e[gwarp * 2 + 0] = m0;
        g_tok_e[gwarp * 2 + 1] = m1;
        g_tok_w[gwarp * 2 + 0] = p[m0] * inv;
        g_tok_w[gwarp * 2 + 1] = p[m1] * inv;
        atomicAdd(&g_cnt[m0], 1);
        atomicAdd(&g_cnt[m1], 1);
    }
}

__global__ void k_scan() {
    if (threadIdx.x == 0) {
        int acc = 0;
        for (int e = 0; e < NEXP; e++) { g_off[e] = acc; acc += g_cnt[e]; g_cur[e] = 0; }
    }
}

__global__ void k_slot() {
    int p = blockIdx.x * blockDim.x + threadIdx.x;
    if (p >= NPAIRS) return;
    int e = g_tok_e[p];
    int r = atomicAdd(&g_cur[e], 1);
    int slot = g_off[e] + r;
    g_pair_tok[slot] = p >> 1;
    g_tok_slot[p] = slot;
}

// ---------------- grouped GEMMs (fp32 SIMT 128x128x8 tiles) ----------------
#define BM 128
#define BN 128
#define BK 8

// h[slot, n] = relu( x[tok(slot), :] @ w1[e][n, :] + b1[e][n] )   K = DM
__global__ void __launch_bounds__(256) k_ffn1(const float* __restrict__ x,
                                              const float* __restrict__ w1,
                                              const float* __restrict__ b1) {
    int e = blockIdx.z;
    int cnt = g_cnt[e];
    int m0 = blockIdx.y * BM;
    if (m0 >= cnt) return;
    int base = g_off[e];
    int n0 = blockIdx.x * BN;
    const float* wb = w1 + (size_t)e * HID * DM + (size_t)n0 * DM;

    __shared__ float As[BK][BM];
    __shared__ float Bs[BK][BN];
    __shared__ int   ts[BM];

    int tid = threadIdx.x;
    for (int i = tid; i < BM; i += 256) {
        int gm = m0 + i;
        ts[i] = (gm < cnt) ? g_pair_tok[base + gm] : -1;
    }
    __syncthreads();

    int lrow = tid >> 1;
    int lk   = (tid & 1) * 4;
    int tx = tid & 15, ty = tid >> 4;

    float acc[8][8];
    #pragma unroll
    for (int i = 0; i < 8; i++)
        #pragma unroll
        for (int j = 0; j < 8; j++) acc[i][j] = 0.f;

    int tok = ts[lrow];
    const float* arow = (tok >= 0) ? (x + (size_t)tok * DM) : x;
    const float* brow = wb + (size_t)lrow * DM;

    for (int k0 = 0; k0 < DM; k0 += BK) {
        float4 av = make_float4(0.f, 0.f, 0.f, 0.f);
        if (tok >= 0) av = *(const float4*)(arow + k0 + lk);
        As[lk + 0][lrow] = av.x; As[lk + 1][lrow] = av.y;
        As[lk + 2][lrow] = av.z; As[lk + 3][lrow] = av.w;
        float4 bv = *(const float4*)(brow + k0 + lk);
        Bs[lk + 0][lrow] = bv.x; Bs[lk + 1][lrow] = bv.y;
        Bs[lk + 2][lrow] = bv.z; Bs[lk + 3][lrow] = bv.w;
        __syncthreads();

        #pragma unroll
        for (int kk = 0; kk < BK; kk++) {
            float4 a0 = *(float4*)&As[kk][ty * 8];
            float4 a1 = *(float4*)&As[kk][ty * 8 + 4];
            float4 b0 = *(float4*)&Bs[kk][tx * 8];
            float4 b1v = *(float4*)&Bs[kk][tx * 8 + 4];
            float a[8] = {a0.x, a0.y, a0.z, a0.w, a1.x, a1.y, a1.z, a1.w};
            float b[8] = {b0.x, b0.y, b0.z, b0.w, b1v.x, b1v.y, b1v.z, b1v.w};
            #pragma unroll
            for (int i = 0; i < 8; i++)
                #pragma unroll
                for (int j = 0; j < 8; j++) acc[i][j] += a[i] * b[j];
        }
        __syncthreads();
    }

    float bias[8];
    #pragma unroll
    for (int j = 0; j < 8; j++) bias[j] = b1[e * HID + n0 + tx * 8 + j];

    #pragma unroll
    for (int i = 0; i < 8; i++) {
        int gm = m0 + ty * 8 + i;
        if (gm < cnt) {
            float* hr = g_h + (size_t)(base + gm) * HID + n0 + tx * 8;
            float4 v0, v1;
            v0.x = fmaxf(acc[i][0] + bias[0], 0.f);
            v0.y = fmaxf(acc[i][1] + bias[1], 0.f);
            v0.z = fmaxf(acc[i][2] + bias[2], 0.f);
            v0.w = fmaxf(acc[i][3] + bias[3], 0.f);
            v1.x = fmaxf(acc[i][4] + bias[4], 0.f);
            v1.y = fmaxf(acc[i][5] + bias[5], 0.f);
            v1.z = fmaxf(acc[i][6] + bias[6], 0.f);
            v1.w = fmaxf(acc[i][7] + bias[7], 0.f);
            *(float4*)(hr + 0) = v0;
            *(float4*)(hr + 4) = v1;
        }
    }
}

// y[slot, n] = h[slot, :] @ w2[e][n, :] + b2[e][n]   K = HID
__global__ void __launch_bounds__(256) k_ffn2(const float* __restrict__ w2,
                                              const float* __restrict__ b2) {
    int e = blockIdx.z;
    int cnt = g_cnt[e];
    int m0 = blockIdx.y * BM;
    if (m0 >= cnt) return;
    int base = g_off[e];
    int n0 = blockIdx.x * BN;
    int mrem = cnt - m0;
    const float* Ab = g_h + (size_t)(base + m0) * HID;
    const float* wb = w2 + (size_t)e * DM * HID + (size_t)n0 * HID;

    __shared__ float As[BK][BM];
    __shared__ float Bs[BK][BN];

    int tid = threadIdx.x;
    int lrow = tid >> 1;
    int lk   = (tid & 1) * 4;
    int tx = tid & 15, ty = tid >> 4;

    float acc[8][8];
    #pragma unroll
    for (int i = 0; i < 8; i++)
        #pragma unroll
        for (int j = 0; j < 8; j++) acc[i][j] = 0.f;

    bool avalid = (lrow < mrem);
    const float* arow = Ab + (size_t)lrow * HID;
    const float* brow = wb + (size_t)lrow * HID;

    for (int k0 = 0; k0 < HID; k0 += BK) {
        float4 av = make_float4(0.f, 0.f, 0.f, 0.f);
        if (avalid) av = *(const float4*)(arow + k0 + lk);
        As[lk + 0][lrow] = av.x; As[lk + 1][lrow] = av.y;
        As[lk + 2][lrow] = av.z; As[lk + 3][lrow] = av.w;
        float4 bv = *(const float4*)(brow + k0 + lk);
        Bs[lk + 0][lrow] = bv.x; Bs[lk + 1][lrow] = bv.y;
        Bs[lk + 2][lrow] = bv.z; Bs[lk + 3][lrow] = bv.w;
        __syncthreads();

        #pragma unroll
        for (int kk = 0; kk < BK; kk++) {
            float4 a0 = *(float4*)&As[kk][ty * 8];
            float4 a1 = *(float4*)&As[kk][ty * 8 + 4];
            float4 b0 = *(float4*)&Bs[kk][tx * 8];
            float4 b1v = *(float4*)&Bs[kk][tx * 8 + 4];
            float a[8] = {a0.x, a0.y, a0.z, a0.w, a1.x, a1.y, a1.z, a1.w};
            float b[8] = {b0.x, b0.y, b0.z, b0.w, b1v.x, b1v.y, b1v.z, b1v.w};
            #pragma unroll
            for (int i = 0; i < 8; i++)
                #pragma unroll
                for (int j = 0; j < 8; j++) acc[i][j] += a[i] * b[j];
        }
        __syncthreads();
    }

    float bias[8];
    #pragma unroll
    for (int j = 0; j < 8; j++) bias[j] = b2[e * DM + n0 + tx * 8 + j];

    #pragma unroll
    for (int i = 0; i < 8; i++) {
        int gm = m0 + ty * 8 + i;
        if (gm < cnt) {
            float* yr = g_y + (size_t)(base + gm) * DM + n0 + tx * 8;
            float4 v0, v1;
            v0.x = acc[i][0] + bias[0]; v0.y = acc[i][1] + bias[1];
            v0.z = acc[i][2] + bias[2]; v0.w = acc[i][3] + bias[3];
            v1.x = acc[i][4] + bias[4]; v1.y = acc[i][5] + bias[5];
            v1.z = acc[i][6] + bias[6]; v1.w = acc[i][7] + bias[7];
            *(float4*)(yr + 0) = v0;
            *(float4*)(yr + 4) = v1;
        }
    }
}

// out[t] = w0 * y[slot0] + w1 * y[slot1]
__global__ void k_combine(float* __restrict__ out) {
    int t = blockIdx.x;
    int d4 = threadIdx.x * 4;
    int s0 = g_tok_slot[t * 2 + 0];
    int s1 = g_tok_slot[t * 2 + 1];
    float w0 = g_tok_w[t * 2 + 0];
    float w1 = g_tok_w[t * 2 + 1];
    float4 y0 = *(const float4*)(g_y + (size_t)s0 * DM + d4);
    float4 y1 = *(const float4*)(g_y + (size_t)s1 * DM + d4);
    float4 r;
    r.x = w0 * y0.x + w1 * y1.x;
    r.y = w0 * y0.y + w1 * y1.y;
    r.z = w0 * y0.z + w1 * y1.z;
    r.w = w0 * y0.w + w1 * y1.w;
    *(float4*)(out + (size_t)t * DM + d4) = r;
}

// ---------------- launch ----------------
extern "C" void kernel_launch(void* const* d_in, const int* in_sizes, int n_in,
                              void* d_out, int out_size) {
    const float* x  = (const float*)d_in[0];
    const float* gw = (const float*)d_in[1];
    const float* w1 = (const float*)d_in[2];
    const float* b1 = (const float*)d_in[3];
    const float* w2 = (const float*)d_in[4];
    const float* b2 = (const float*)d_in[5];
    float* out = (float*)d_out;

    k_zero<<<1, 32>>>();
    k_router<<<NTOK / 8, 256>>>(x, gw);
    k_scan<<<1, 32>>>();
    k_slot<<<NPAIRS / 256, 256>>>();
    k_ffn1<<<dim3(HID / BN, NPAIRS / BM, NEXP), 256>>>(x, w1, b1);
    k_ffn2<<<dim3(DM / BN, NPAIRS / BM, NEXP), 256>>>(w2, b2);
    k_combine<<<NTOK, 256>>>(out);
}

// round 3
// speedup vs baseline: 2.8138x; 2.8138x over previous
#include <cuda_runtime.h>
#include <cstdint>

// Problem constants
#define NTOK   4096
#define DM     1024
#define HID    4096
#define NEXP   8
#define NPAIRS (NTOK*2)      // 8192 (token, k) pairs

// ---------------- scratch (allocation-free __device__ globals) ----------------
__device__ float g_xg[(size_t)NPAIRS * DM];   // gathered activations per slot
__device__ float g_h [(size_t)NPAIRS * HID];  // hidden per slot
__device__ float g_y [(size_t)NPAIRS * DM];   // expert outputs per slot
__device__ int   g_tok_e[NPAIRS];
__device__ float g_tok_w[NPAIRS];
__device__ int   g_tok_slot[NPAIRS];
__device__ int   g_pair_tok[NPAIRS];
__device__ int   g_cnt[NEXP];
__device__ int   g_off[NEXP];
__device__ int   g_cur[NEXP];

// ---------------- portable PTX helpers (no "a"-suffix features) ----------------
__device__ __forceinline__ uint32_t smem_u32(const void* p) {
    uint32_t a;
    asm("{ .reg .u64 t; cvta.to.shared.u64 t, %1; cvt.u32.u64 %0, t; }" : "=r"(a) : "l"(p));
    return a;
}
__device__ __forceinline__ uint32_t f2tf(float x) {
    uint32_t u; asm("cvt.rna.tf32.f32 %0, %1;" : "=r"(u) : "f"(x)); return u;
}
__device__ __forceinline__ void mma_tf32(float* c, const uint32_t* a, const uint32_t* b) {
    asm volatile("mma.sync.aligned.m16n8k8.row.col.f32.tf32.tf32.f32 "
        "{%0,%1,%2,%3}, {%4,%5,%6,%7}, {%8,%9}, {%0,%1,%2,%3};"
        : "+f"(c[0]), "+f"(c[1]), "+f"(c[2]), "+f"(c[3])
        : "r"(a[0]), "r"(a[1]), "r"(a[2]), "r"(a[3]), "r"(b[0]), "r"(b[1]));
}
__device__ __forceinline__ void cp16(uint32_t saddr, const void* g, bool pred) {
    int sz = pred ? 16 : 0;
    asm volatile("cp.async.cg.shared.global [%0], [%1], 16, %2;"
                 :: "r"(saddr), "l"(g), "r"(sz));
}
#define CP_COMMIT() asm volatile("cp.async.commit_group;" ::: "memory")
#define CP_WAIT(n)  asm volatile("cp.async.wait_group %0;" :: "n"(n) : "memory")

// ---------------- tiny routing kernels ----------------
__global__ void k_zero() { if (threadIdx.x < NEXP) g_cnt[threadIdx.x] = 0; }

__global__ void k_router(const float* __restrict__ x, const float* __restrict__ gw) {
    int t = (blockIdx.x * blockDim.x + threadIdx.x) >> 5;
    int lane = threadIdx.x & 31;
    if (t >= NTOK) return;
    const float* xr = x + (size_t)t * DM;
    float logit[NEXP];
    #pragma unroll
    for (int e = 0; e < NEXP; e++) {
        const float* wr = gw + e * DM;
        float s = 0.f;
        for (int i = lane; i < DM; i += 32) s += xr[i] * wr[i];
        #pragma unroll
        for (int o = 16; o; o >>= 1) s += __shfl_xor_sync(0xffffffffu, s, o);
        logit[e] = s;
    }
    if (lane == 0) {
        float mx = logit[0];
        #pragma unroll
        for (int e = 1; e < NEXP; e++) mx = fmaxf(mx, logit[e]);
        float p[NEXP], den = 0.f;
        #pragma unroll
        for (int e = 0; e < NEXP; e++) { p[e] = expf(logit[e] - mx); den += p[e]; }
        float inv = 1.f / den;
        int m0 = 0;
        #pragma unroll
        for (int e = 1; e < NEXP; e++) if (p[e] > p[m0]) m0 = e;
        int m1 = (m0 == 0) ? 1 : 0;
        #pragma unroll
        for (int e = 0; e < NEXP; e++) if (e != m0 && p[e] > p[m1]) m1 = e;
        g_tok_e[t * 2 + 0] = m0;  g_tok_e[t * 2 + 1] = m1;
        g_tok_w[t * 2 + 0] = p[m0] * inv;  g_tok_w[t * 2 + 1] = p[m1] * inv;
        atomicAdd(&g_cnt[m0], 1);  atomicAdd(&g_cnt[m1], 1);
    }
}

__global__ void k_scan() {
    if (threadIdx.x == 0) {
        int acc = 0;
        for (int e = 0; e < NEXP; e++) { g_off[e] = acc; acc += g_cnt[e]; g_cur[e] = 0; }
    }
}

__global__ void k_slot() {
    int p = blockIdx.x * blockDim.x + threadIdx.x;
    if (p >= NPAIRS) return;
    int e = g_tok_e[p];
    int slot = g_off[e] + atomicAdd(&g_cur[e], 1);
    g_pair_tok[slot] = p >> 1;
    g_tok_slot[p] = slot;
}

__global__ void k_gather(const float* __restrict__ x) {
    int slot = blockIdx.x;
    int tok = g_pair_tok[slot];
    const float4* s = (const float4*)(x + (size_t)tok * DM);
    float4* d = (float4*)(g_xg + (size_t)slot * DM);
    d[threadIdx.x] = s[threadIdx.x];
}

// ---------------- tf32 mma.sync grouped GEMM ----------------
// tile: BM=128 x BN=128 x BK=16, 256 threads = 8 warps (2 M x 4 N), warp 64x32
#define BM 128
#define BN 128
#define BK 16
#define STAGES 4
#define ROWF   20                      // BK + 4 pad (floats); 80B, 16B-aligned rows
#define STG_F  (2 * 128 * ROWF)        // floats per stage (A then B)
#define STG_B  (STG_F * 4)             // bytes per stage = 20480
#define SM_TOTAL (STAGES * STG_B)      // 81920

template<int KTOT, bool RELU>
__global__ void __launch_bounds__(256, 2) k_gemm(const float* __restrict__ A,   // [slots, KTOT]
                                                 const float* __restrict__ B,   // [NEXP*n_total, KTOT]
                                                 const float* __restrict__ bias,// [NEXP*n_total]
                                                 float* __restrict__ C,         // [slots, n_total]
                                                 int n_total) {
    int e = blockIdx.z;
    int cnt = g_cnt[e];
    int m0 = blockIdx.y * BM;
    if (m0 >= cnt) return;
    int base = g_off[e];
    int n0 = blockIdx.x * BN;
    int mrem = cnt - m0;

    extern __shared__ float smf[];
    uint32_t sb = smem_u32(smf);
    int tid = threadIdx.x;
    int wid = tid >> 5, lane = tid & 31;
    int gp = lane >> 2, tg = lane & 3;
    int wm = (wid & 1) * 64;          // warp M offset in tile
    int wn = (wid >> 1) * 32;         // warp N offset in tile

    const float* Ab = A + (size_t)(base + m0) * KTOT;
    const float* Bb = B + ((size_t)e * n_total + n0) * KTOT;

    // loader tasks: A = 512 (128 rows x 4 chunks of 16B), B = 512
    int ar0 = tid >> 2,        ac0 = tid & 3;          // tasks tid, tid+256
    int ar1 = (tid + 256) >> 2, ac1 = (tid + 256) & 3;

    auto load_stage = [&](int c, int buf) {
        int k0 = c * BK;
        uint32_t abase = sb + buf * STG_B;
        uint32_t bbase = abase + 128 * ROWF * 4;
        cp16(abase + (ar0 * ROWF + ac0 * 4) * 4, Ab + (size_t)ar0 * KTOT + k0 + ac0 * 4, ar0 < mrem);
        cp16(abase + (ar1 * ROWF + ac1 * 4) * 4, Ab + (size_t)ar1 * KTOT + k0 + ac1 * 4, ar1 < mrem);
        cp16(bbase + (ar0 * ROWF + ac0 * 4) * 4, Bb + (size_t)ar0 * KTOT + k0 + ac0 * 4, true);
        cp16(bbase + (ar1 * ROWF + ac1 * 4) * 4, Bb + (size_t)ar1 * KTOT + k0 + ac1 * 4, true);
    };

    float acc[4][4][4];
    #pragma unroll
    for (int i = 0; i < 4; i++)
        #pragma unroll
        for (int j = 0; j < 4; j++)
            #pragma unroll
            for (int q = 0; q < 4; q++) acc[i][j][q] = 0.f;

    constexpr int NC = KTOT / BK;

    #pragma unroll
    for (int s = 0; s < STAGES - 1; s++) {
        load_stage(s, s);
        CP_COMMIT();
    }

    #pragma unroll 1
    for (int c = 0; c < NC; c++) {
        CP_WAIT(STAGES - 2);
        __syncthreads();

        if (c + STAGES - 1 < NC) load_stage(c + STAGES - 1, (c + STAGES - 1) % STAGES);
        CP_COMMIT();

        const float* As = smf + (c % STAGES) * STG_F;
        const float* Bs = As + 128 * ROWF;

        #pragma unroll
        for (int kk = 0; kk < 2; kk++) {
            int k0 = kk * 8;
            uint32_t af[4][4], bf[4][2];
            #pragma unroll
            for (int mi = 0; mi < 4; mi++) {
                const float* ap = As + (wm + mi * 16 + gp) * ROWF + k0 + tg;
                af[mi][0] = f2tf(ap[0]);
                af[mi][1] = f2tf(ap[8 * ROWF]);
                af[mi][2] = f2tf(ap[4]);
                af[mi][3] = f2tf(ap[8 * ROWF + 4]);
            }
            #pragma unroll
            for (int ni = 0; ni < 4; ni++) {
                const float* bp = Bs + (wn + ni * 8 + gp) * ROWF + k0 + tg;
                bf[ni][0] = f2tf(bp[0]);
                bf[ni][1] = f2tf(bp[4]);
            }
            #pragma unroll
            for (int mi = 0; mi < 4; mi++)
                #pragma unroll
                for (int ni = 0; ni < 4; ni++)
                    mma_tf32(acc[mi][ni], af[mi], bf[ni]);
        }
        __syncthreads();
    }

    // epilogue: bias (+relu), store
    const float* brow = bias + (size_t)e * n_total + n0;
    #pragma unroll
    for (int ni = 0; ni < 4; ni++) {
        int col = wn + ni * 8 + tg * 2;
        float b0 = brow[col], b1 = brow[col + 1];
        #pragma unroll
        for (int mi = 0; mi < 4; mi++) {
            int r0 = wm + mi * 16 + gp;
            float v0 = acc[mi][ni][0] + b0, v1 = acc[mi][ni][1] + b1;
            float v2 = acc[mi][ni][2] + b0, v3 = acc[mi][ni][3] + b1;
            if (RELU) {
                v0 = fmaxf(v0, 0.f); v1 = fmaxf(v1, 0.f);
                v2 = fmaxf(v2, 0.f); v3 = fmaxf(v3, 0.f);
            }
            if (r0 < mrem) {
                float* cr = C + (size_t)(base + m0 + r0) * n_total + n0 + col;
                cr[0] = v0; cr[1] = v1;
            }
            if (r0 + 8 < mrem) {
                float* cr = C + (size_t)(base + m0 + r0 + 8) * n_total + n0 + col;
                cr[0] = v2; cr[1] = v3;
            }
        }
    }
}

// out[t] = w0 * y[slot0] + w1 * y[slot1]
__global__ void k_combine(float* __restrict__ out) {
    int t = blockIdx.x;
    int d4 = threadIdx.x * 4;
    int s0 = g_tok_slot[t * 2 + 0], s1 = g_tok_slot[t * 2 + 1];
    float w0 = g_tok_w[t * 2 + 0],  w1 = g_tok_w[t * 2 + 1];
    float4 y0 = *(const float4*)(g_y + (size_t)s0 * DM + d4);
    float4 y1 = *(const float4*)(g_y + (size_t)s1 * DM + d4);
    float4 r;
    r.x = w0 * y0.x + w1 * y1.x;  r.y = w0 * y0.y + w1 * y1.y;
    r.z = w0 * y0.z + w1 * y1.z;  r.w = w0 * y0.w + w1 * y1.w;
    *(float4*)(out + (size_t)t * DM + d4) = r;
}

// ---------------- launch ----------------
extern "C" void kernel_launch(void* const* d_in, const int* in_sizes, int n_in,
                              void* d_out, int out_size) {
    const float* x  = (const float*)d_in[0];
    const float* gw = (const float*)d_in[1];
    const float* w1 = (const float*)d_in[2];
    const float* b1 = (const float*)d_in[3];
    const float* w2 = (const float*)d_in[4];
    const float* b2 = (const float*)d_in[5];
    float* out = (float*)d_out;

    cudaFuncSetAttribute(k_gemm<DM, true>,   cudaFuncAttributeMaxDynamicSharedMemorySize, SM_TOTAL);
    cudaFuncSetAttribute(k_gemm<HID, false>, cudaFuncAttributeMaxDynamicSharedMemorySize, SM_TOTAL);

    float* xg; cudaGetSymbolAddress((void**)&xg, g_xg);
    float* hh; cudaGetSymbolAddress((void**)&hh, g_h);
    float* yy; cudaGetSymbolAddress((void**)&yy, g_y);

    k_zero<<<1, 32>>>();
    k_router<<<NTOK / 8, 256>>>(x, gw);
    k_scan<<<1, 32>>>();
    k_slot<<<NPAIRS / 256, 256>>>();
    k_gather<<<NPAIRS, 256>>>(x);
    // GEMM1: [slots,1024] x w1[e][4096,1024]^T -> g_h [slots,4096], bias+relu
    k_gemm<DM, true><<<dim3(HID / BN, NPAIRS / BM, NEXP), 256, SM_TOTAL>>>(xg, w1, b1, hh, HID);
    // GEMM2: [slots,4096] x w2[e][1024,4096]^T -> g_y [slots,1024], bias
    k_gemm<HID, false><<<dim3(DM / BN, NPAIRS / BM, NEXP), 256, SM_TOTAL>>>(hh, w2, b2, yy, DM);
    k_combine<<<NTOK, 256>>>(out);
}

// round 4
// speedup vs baseline: 5.0227x; 1.7850x over previous
#include <cuda_runtime.h>
#include <cuda_fp16.h>
#include <cstdint>

// Problem constants
#define NTOK   4096
#define DM     1024
#define HID    4096
#define NEXP   8
#define NPAIRS (NTOK*2)      // 8192 (token, k) pairs

// ---------------- scratch (allocation-free __device__ globals) ----------------
__device__ __half g_w1h[(size_t)NEXP * HID * DM];   // fp16 copy of w1 (67MB)
__device__ __half g_w2h[(size_t)NEXP * DM * HID];   // fp16 copy of w2 (67MB)
__device__ __half g_xgh[(size_t)NPAIRS * DM];       // gathered activations (fp16)
__device__ __half g_h  [(size_t)NPAIRS * HID];      // hidden per slot (fp16)
__device__ float  g_y  [(size_t)NPAIRS * DM];       // expert outputs (fp32)
__device__ int    g_tok_e[NPAIRS];
__device__ float  g_tok_w[NPAIRS];
__device__ int    g_tok_slot[NPAIRS];
__device__ int    g_pair_tok[NPAIRS];
__device__ int    g_cnt[NEXP];
__device__ int    g_off[NEXP];
__device__ int    g_cur[NEXP];

// ---------------- portable PTX helpers ----------------
__device__ __forceinline__ uint32_t smem_u32(const void* p) {
    uint32_t a;
    asm("{ .reg .u64 t; cvta.to.shared.u64 t, %1; cvt.u32.u64 %0, t; }" : "=r"(a) : "l"(p));
    return a;
}
__device__ __forceinline__ void ldsm_x4(uint32_t* r, uint32_t addr) {
    asm volatile("ldmatrix.sync.aligned.m8n8.x4.shared.b16 {%0,%1,%2,%3}, [%4];"
        : "=r"(r[0]), "=r"(r[1]), "=r"(r[2]), "=r"(r[3]) : "r"(addr));
}
__device__ __forceinline__ void mma_f16(float* c, const uint32_t* a, const uint32_t* b) {
    asm volatile("mma.sync.aligned.m16n8k16.row.col.f32.f16.f16.f32 "
        "{%0,%1,%2,%3}, {%4,%5,%6,%7}, {%8,%9}, {%0,%1,%2,%3};"
        : "+f"(c[0]), "+f"(c[1]), "+f"(c[2]), "+f"(c[3])
        : "r"(a[0]), "r"(a[1]), "r"(a[2]), "r"(a[3]), "r"(b[0]), "r"(b[1]));
}
__device__ __forceinline__ void cp16(uint32_t saddr, const void* g, bool pred) {
    int sz = pred ? 16 : 0;
    asm volatile("cp.async.cg.shared.global [%0], [%1], 16, %2;"
                 :: "r"(saddr), "l"(g), "r"(sz));
}
#define CP_COMMIT() asm volatile("cp.async.commit_group;" ::: "memory")
#define CP_WAIT(n)  asm volatile("cp.async.wait_group %0;" :: "n"(n) : "memory")

// ---------------- tiny routing kernels ----------------
__global__ void k_zero() { if (threadIdx.x < NEXP) g_cnt[threadIdx.x] = 0; }

__global__ void k_router(const float* __restrict__ x, const float* __restrict__ gw) {
    int t = (blockIdx.x * blockDim.x + threadIdx.x) >> 5;
    int lane = threadIdx.x & 31;
    if (t >= NTOK) return;
    const float* xr = x + (size_t)t * DM;
    float logit[NEXP];
    #pragma unroll
    for (int e = 0; e < NEXP; e++) {
        const float* wr = gw + e * DM;
        float s = 0.f;
        for (int i = lane; i < DM; i += 32) s += xr[i] * wr[i];
        #pragma unroll
        for (int o = 16; o; o >>= 1) s += __shfl_xor_sync(0xffffffffu, s, o);
        logit[e] = s;
    }
    if (lane == 0) {
        float mx = logit[0];
        #pragma unroll
        for (int e = 1; e < NEXP; e++) mx = fmaxf(mx, logit[e]);
        float p[NEXP], den = 0.f;
        #pragma unroll
        for (int e = 0; e < NEXP; e++) { p[e] = expf(logit[e] - mx); den += p[e]; }
        float inv = 1.f / den;
        int m0 = 0;
        #pragma unroll
        for (int e = 1; e < NEXP; e++) if (p[e] > p[m0]) m0 = e;
        int m1 = (m0 == 0) ? 1 : 0;
        #pragma unroll
        for (int e = 0; e < NEXP; e++) if (e != m0 && p[e] > p[m1]) m1 = e;
        g_tok_e[t * 2 + 0] = m0;  g_tok_e[t * 2 + 1] = m1;
        g_tok_w[t * 2 + 0] = p[m0] * inv;  g_tok_w[t * 2 + 1] = p[m1] * inv;
        atomicAdd(&g_cnt[m0], 1);  atomicAdd(&g_cnt[m1], 1);
    }
}

__global__ void k_scan() {
    if (threadIdx.x == 0) {
        int acc = 0;
        for (int e = 0; e < NEXP; e++) { g_off[e] = acc; acc += g_cnt[e]; g_cur[e] = 0; }
    }
}

__global__ void k_slot() {
    int p = blockIdx.x * blockDim.x + threadIdx.x;
    if (p >= NPAIRS) return;
    int e = g_tok_e[p];
    int slot = g_off[e] + atomicAdd(&g_cur[e], 1);
    g_pair_tok[slot] = p >> 1;
    g_tok_slot[p] = slot;
}

// fp32 -> fp16 weight conversion (grid exactly covers n/8)
__global__ void k_cvt(const float* __restrict__ src, __half* __restrict__ dst) {
    size_t i = ((size_t)blockIdx.x * blockDim.x + threadIdx.x) * 8;
    float4 f0 = *(const float4*)(src + i);
    float4 f1 = *(const float4*)(src + i + 4);
    __half2 h[4];
    h[0] = __floats2half2_rn(f0.x, f0.y);
    h[1] = __floats2half2_rn(f0.z, f0.w);
    h[2] = __floats2half2_rn(f1.x, f1.y);
    h[3] = __floats2half2_rn(f1.z, f1.w);
    *(uint4*)(dst + i) = *(uint4*)h;
}

// gather + convert x rows to fp16
__global__ void k_gather(const float* __restrict__ x) {
    int slot = blockIdx.x;
    int tok = g_pair_tok[slot];
    int d4 = threadIdx.x * 4;
    float4 v = *(const float4*)(x + (size_t)tok * DM + d4);
    __half2 h[2] = {__floats2half2_rn(v.x, v.y), __floats2half2_rn(v.z, v.w)};
    *(uint2*)(g_xgh + (size_t)slot * DM + d4) = *(uint2*)h;
}

// ---------------- fp16 mma.sync grouped GEMM ----------------
// tile: BM=128 x BN=128 x BK=16, 256 threads = 8 warps (2M x 4N), warp 64x32
// smem row pitch 48B (conflict-free ldmatrix + padded cp.async)
#define BM 128
#define BN 128
#define BK 16
#define STAGES 4
#define PITCH 48                         // bytes per 16-half row (32B data + 16B pad)
#define A_BYTES (128 * PITCH)            // 6144
#define STG_B   (2 * A_BYTES)            // 12288
#define SM_TOTAL (STAGES * STG_B)        // 49152

template<int KTOT, bool RELU, typename OutT>
__global__ void __launch_bounds__(256, 2) k_gemm(const __half* __restrict__ A,  // [slots, KTOT]
                                                 const __half* __restrict__ B,  // [NEXP*n_total, KTOT]
                                                 const float* __restrict__ bias,
                                                 OutT* __restrict__ C,          // [slots, n_total]
                                                 int n_total) {
    int e = blockIdx.z;
    int cnt = g_cnt[e];
    int m0 = blockIdx.y * BM;
    if (m0 >= cnt) return;
    int base = g_off[e];
    int n0 = blockIdx.x * BN;
    int mrem = cnt - m0;

    extern __shared__ char smc[];
    uint32_t sb = smem_u32(smc);
    int tid = threadIdx.x;
    int wid = tid >> 5, lane = tid & 31;
    int gp = lane >> 2, tg = lane & 3;
    int wm = (wid & 1) * 64;          // warp M offset
    int wn = (wid >> 1) * 32;         // warp N offset

    const __half* Ab = A + (size_t)(base + m0) * KTOT;
    const __half* Bb = B + ((size_t)e * n_total + n0) * KTOT;

    // loader: thread -> (row = tid&127, chunk = tid>>7) for both A and B
    int lr = tid & 127, lc = tid >> 7;
    auto load_stage = [&](int c, int buf) {
        int k0 = c * BK;
        uint32_t st = sb + buf * STG_B;
        cp16(st + lr * PITCH + lc * 16, Ab + (size_t)lr * KTOT + k0 + lc * 8, lr < mrem);
        cp16(st + A_BYTES + lr * PITCH + lc * 16, Bb + (size_t)lr * KTOT + k0 + lc * 8, true);
    };

    // per-lane ldmatrix source offsets (within a stage)
    int m4 = lane >> 3, ri = lane & 7;
    uint32_t a_off[4], b_off[2];
    #pragma unroll
    for (int mi = 0; mi < 4; mi++)
        a_off[mi] = (uint32_t)((wm + mi * 16 + (m4 & 1) * 8 + ri) * PITCH + (m4 >> 1) * 16);
    #pragma unroll
    for (int nj = 0; nj < 2; nj++)
        b_off[nj] = (uint32_t)(A_BYTES + (wn + nj * 16 + (m4 >> 1) * 8 + ri) * PITCH + (m4 & 1) * 16);

    float acc[4][4][4];
    #pragma unroll
    for (int i = 0; i < 4; i++)
        #pragma unroll
        for (int j = 0; j < 4; j++)
            #pragma unroll
            for (int q = 0; q < 4; q++) acc[i][j][q] = 0.f;

    constexpr int NC = KTOT / BK;

    #pragma unroll
    for (int s = 0; s < STAGES - 1; s++) { load_stage(s, s); CP_COMMIT(); }

    #pragma unroll 1
    for (int c = 0; c < NC; c++) {
        CP_WAIT(STAGES - 2);
        __syncthreads();

        if (c + STAGES - 1 < NC) load_stage(c + STAGES - 1, (c + STAGES - 1) % STAGES);
        CP_COMMIT();

        uint32_t st = sb + (c % STAGES) * STG_B;
        uint32_t af[4][4], bf[2][4];
        #pragma unroll
        for (int mi = 0; mi < 4; mi++) ldsm_x4(af[mi], st + a_off[mi]);
        #pragma unroll
        for (int nj = 0; nj < 2; nj++) ldsm_x4(bf[nj], st + b_off[nj]);

        #pragma unroll
        for (int mi = 0; mi < 4; mi++)
            #pragma unroll
            for (int ni = 0; ni < 4; ni++)
                mma_f16(acc[mi][ni], af[mi], &bf[ni >> 1][(ni & 1) * 2]);
    }

    // epilogue: bias (+relu), store
    const float* brow = bias + (size_t)e * n_total + n0;
    #pragma unroll
    for (int ni = 0; ni < 4; ni++) {
        int col = wn + ni * 8 + tg * 2;
        float b0 = brow[col], b1 = brow[col + 1];
        #pragma unroll
        for (int mi = 0; mi < 4; mi++) {
            int r0 = wm + mi * 16 + gp;
            float v0 = acc[mi][ni][0] + b0, v1 = acc[mi][ni][1] + b1;
            float v2 = acc[mi][ni][2] + b0, v3 = acc[mi][ni][3] + b1;
            if (RELU) {
                v0 = fmaxf(v0, 0.f); v1 = fmaxf(v1, 0.f);
                v2 = fmaxf(v2, 0.f); v3 = fmaxf(v3, 0.f);
            }
            if (r0 < mrem) {
                OutT* cr = C + (size_t)(base + m0 + r0) * n_total + n0 + col;
                if constexpr (sizeof(OutT) == 2) {
                    *(__half2*)cr = __floats2half2_rn(v0, v1);
                } else { cr[0] = v0; cr[1] = v1; }
            }
            if (r0 + 8 < mrem) {
                OutT* cr = C + (size_t)(base + m0 + r0 + 8) * n_total + n0 + col;
                if constexpr (sizeof(OutT) == 2) {
                    *(__half2*)cr = __floats2half2_rn(v2, v3);
                } else { cr[0] = v2; cr[1] = v3; }
            }
        }
    }
}

// out[t] = w0 * y[slot0] + w1 * y[slot1]
__global__ void k_combine(float* __restrict__ out) {
    int t = blockIdx.x;
    int d4 = threadIdx.x * 4;
    int s0 = g_tok_slot[t * 2 + 0], s1 = g_tok_slot[t * 2 + 1];
    float w0 = g_tok_w[t * 2 + 0],  w1 = g_tok_w[t * 2 + 1];
    float4 y0 = *(const float4*)(g_y + (size_t)s0 * DM + d4);
    float4 y1 = *(const float4*)(g_y + (size_t)s1 * DM + d4);
    float4 r;
    r.x = w0 * y0.x + w1 * y1.x;  r.y = w0 * y0.y + w1 * y1.y;
    r.z = w0 * y0.z + w1 * y1.z;  r.w = w0 * y0.w + w1 * y1.w;
    *(float4*)(out + (size_t)t * DM + d4) = r;
}

// ---------------- launch ----------------
extern "C" void kernel_launch(void* const* d_in, const int* in_sizes, int n_in,
                              void* d_out, int out_size) {
    const float* x  = (const float*)d_in[0];
    const float* gw = (const float*)d_in[1];
    const float* w1 = (const float*)d_in[2];
    const float* b1 = (const float*)d_in[3];
    const float* w2 = (const float*)d_in[4];
    const float* b2 = (const float*)d_in[5];
    float* out = (float*)d_out;

    cudaFuncSetAttribute((const void*)k_gemm<DM, true, __half>,   cudaFuncAttributeMaxDynamicSharedMemorySize, SM_TOTAL);
    cudaFuncSetAttribute((const void*)k_gemm<HID, false, float>,  cudaFuncAttributeMaxDynamicSharedMemorySize, SM_TOTAL);

    __half* w1h; cudaGetSymbolAddress((void**)&w1h, g_w1h);
    __half* w2h; cudaGetSymbolAddress((void**)&w2h, g_w2h);
    __half* xgh; cudaGetSymbolAddress((void**)&xgh, g_xgh);
    __half* hh;  cudaGetSymbolAddress((void**)&hh,  g_h);
    float*  yy;  cudaGetSymbolAddress((void**)&yy,  g_y);

    const size_t WN = (size_t)NEXP * HID * DM;     // 33.55M elements
    k_cvt<<<(int)(WN / 8 / 256), 256>>>(w1, w1h);
    k_cvt<<<(int)(WN / 8 / 256), 256>>>(w2, w2h);

    k_zero<<<1, 32>>>();
    k_router<<<NTOK / 8, 256>>>(x, gw);
    k_scan<<<1, 32>>>();
    k_slot<<<NPAIRS / 256, 256>>>();
    k_gather<<<NPAIRS, 256>>>(x);
    // GEMM1: [slots,1024]h x w1h[e][4096,1024]^T -> g_h [slots,4096]h, bias+relu
    k_gemm<DM, true, __half><<<dim3(HID / BN, NPAIRS / BM, NEXP), 256, SM_TOTAL>>>(xgh, w1h, b1, hh, HID);
    // GEMM2: [slots,4096]h x w2h[e][1024,4096]^T -> g_y [slots,1024]f, bias
    k_gemm<HID, false, float><<<dim3(DM / BN, NPAIRS / BM, NEXP), 256, SM_TOTAL>>>(hh, w2h, b2, yy, DM);
    k_combine<<<NTOK, 256>>>(out);
}

// round 5
// speedup vs baseline: 5.3234x; 1.0599x over previous
#include <cuda_runtime.h>
#include <cuda_fp16.h>
#include <cstdint>

// Problem constants
#define NTOK   4096
#define DM     1024
#define HID    4096
#define NEXP   8
#define NPAIRS (NTOK*2)      // 8192 (token, k) pairs

// ---------------- scratch (allocation-free __device__ globals) ----------------
__device__ __half g_w1h[(size_t)NEXP * HID * DM];
__device__ __half g_w2h[(size_t)NEXP * DM * HID];
__device__ __half g_xgh[(size_t)NPAIRS * DM];
__device__ __half g_h  [(size_t)NPAIRS * HID];
__device__ float  g_y  [(size_t)NPAIRS * DM];
__device__ int    g_tok_e[NPAIRS];
__device__ float  g_tok_w[NPAIRS];
__device__ int    g_tok_slot[NPAIRS];
__device__ int    g_pair_tok[NPAIRS];
__device__ int    g_cnt[NEXP];
__device__ int    g_off[NEXP];
__device__ int    g_cur[NEXP];

// ---------------- portable PTX helpers ----------------
__device__ __forceinline__ uint32_t smem_u32(const void* p) {
    uint32_t a;
    asm("{ .reg .u64 t; cvta.to.shared.u64 t, %1; cvt.u32.u64 %0, t; }" : "=r"(a) : "l"(p));
    return a;
}
__device__ __forceinline__ void ldsm_x4(uint32_t* r, uint32_t addr) {
    asm volatile("ldmatrix.sync.aligned.m8n8.x4.shared.b16 {%0,%1,%2,%3}, [%4];"
        : "=r"(r[0]), "=r"(r[1]), "=r"(r[2]), "=r"(r[3]) : "r"(addr));
}
__device__ __forceinline__ void mma_f16(float* c, const uint32_t* a, const uint32_t* b) {
    asm volatile("mma.sync.aligned.m16n8k16.row.col.f32.f16.f16.f32 "
        "{%0,%1,%2,%3}, {%4,%5,%6,%7}, {%8,%9}, {%0,%1,%2,%3};"
        : "+f"(c[0]), "+f"(c[1]), "+f"(c[2]), "+f"(c[3])
        : "r"(a[0]), "r"(a[1]), "r"(a[2]), "r"(a[3]), "r"(b[0]), "r"(b[1]));
}
__device__ __forceinline__ void cp16(uint32_t saddr, const void* g, bool pred) {
    int sz = pred ? 16 : 0;
    asm volatile("cp.async.cg.shared.global [%0], [%1], 16, %2;"
                 :: "r"(saddr), "l"(g), "r"(sz));
}
#define CP_COMMIT() asm volatile("cp.async.commit_group;" ::: "memory")
#define CP_WAIT(n)  asm volatile("cp.async.wait_group %0;" :: "n"(n) : "memory")

// ---------------- tiny routing kernels ----------------
__global__ void k_zero() { if (threadIdx.x < NEXP) g_cnt[threadIdx.x] = 0; }

__global__ void k_router(const float* __restrict__ x, const float* __restrict__ gw) {
    int t = (blockIdx.x * blockDim.x + threadIdx.x) >> 5;
    int lane = threadIdx.x & 31;
    if (t >= NTOK) return;
    const float* xr = x + (size_t)t * DM;
    float logit[NEXP];
    #pragma unroll
    for (int e = 0; e < NEXP; e++) {
        const float* wr = gw + e * DM;
        float s = 0.f;
        for (int i = lane; i < DM; i += 32) s += xr[i] * wr[i];
        #pragma unroll
        for (int o = 16; o; o >>= 1) s += __shfl_xor_sync(0xffffffffu, s, o);
        logit[e] = s;
    }
    if (lane == 0) {
        float mx = logit[0];
        #pragma unroll
        for (int e = 1; e < NEXP; e++) mx = fmaxf(mx, logit[e]);
        float p[NEXP], den = 0.f;
        #pragma unroll
        for (int e = 0; e < NEXP; e++) { p[e] = expf(logit[e] - mx); den += p[e]; }
        float inv = 1.f / den;
        int m0 = 0;
        #pragma unroll
        for (int e = 1; e < NEXP; e++) if (p[e] > p[m0]) m0 = e;
        int m1 = (m0 == 0) ? 1 : 0;
        #pragma unroll
        for (int e = 0; e < NEXP; e++) if (e != m0 && p[e] > p[m1]) m1 = e;
        g_tok_e[t * 2 + 0] = m0;  g_tok_e[t * 2 + 1] = m1;
        g_tok_w[t * 2 + 0] = p[m0] * inv;  g_tok_w[t * 2 + 1] = p[m1] * inv;
        atomicAdd(&g_cnt[m0], 1);  atomicAdd(&g_cnt[m1], 1);
    }
}

__global__ void k_scan() {
    if (threadIdx.x == 0) {
        int acc = 0;
        for (int e = 0; e < NEXP; e++) { g_off[e] = acc; acc += g_cnt[e]; g_cur[e] = 0; }
    }
}

__global__ void k_slot() {
    int p = blockIdx.x * blockDim.x + threadIdx.x;
    if (p >= NPAIRS) return;
    int e = g_tok_e[p];
    int slot = g_off[e] + atomicAdd(&g_cur[e], 1);
    g_pair_tok[slot] = p >> 1;
    g_tok_slot[p] = slot;
}

// fp32 -> fp16 weight conversion
__global__ void k_cvt(const float* __restrict__ src, __half* __restrict__ dst) {
    size_t i = ((size_t)blockIdx.x * blockDim.x + threadIdx.x) * 8;
    float4 f0 = *(const float4*)(src + i);
    float4 f1 = *(const float4*)(src + i + 4);
    __half2 h[4];
    h[0] = __floats2half2_rn(f0.x, f0.y);
    h[1] = __floats2half2_rn(f0.z, f0.w);
    h[2] = __floats2half2_rn(f1.x, f1.y);
    h[3] = __floats2half2_rn(f1.z, f1.w);
    *(uint4*)(dst + i) = *(uint4*)h;
}

// gather + convert x rows to fp16
__global__ void k_gather(const float* __restrict__ x) {
    int slot = blockIdx.x;
    int tok = g_pair_tok[slot];
    int d4 = threadIdx.x * 4;
    float4 v = *(const float4*)(x + (size_t)tok * DM + d4);
    __half2 h[2] = {__floats2half2_rn(v.x, v.y), __floats2half2_rn(v.z, v.w)};
    *(uint2*)(g_xgh + (size_t)slot * DM + d4) = *(uint2*)h;
}

// ---------------- fp16 mma.sync grouped GEMM ----------------
// CTA tile 128x256x16, 8 warps (2M x 2N), warp tile 64x64
#define BM 128
#define BN 256
#define BK 16
#define STAGES 4
#define PITCH 48                          // bytes per 16-half row (32B data + 16B pad)
#define A_BYTES (BM * PITCH)              // 6144
#define B_BYTES (BN * PITCH)              // 12288
#define STG_B   (A_BYTES + B_BYTES)       // 18432
#define SM_TOTAL (STAGES * STG_B)         // 73728

template<int KTOT, bool RELU, typename OutT>
__global__ void __launch_bounds__(256, 1) k_gemm(const __half* __restrict__ A,  // [slots, KTOT]
                                                 const __half* __restrict__ B,  // [NEXP*n_total, KTOT]
                                                 const float* __restrict__ bias,
                                                 OutT* __restrict__ C,          // [slots, n_total]
                                                 int n_total) {
    int e = blockIdx.z;
    int cnt = g_cnt[e];
    int m0 = blockIdx.y * BM;
    if (m0 >= cnt) return;
    int base = g_off[e];
    int n0 = blockIdx.x * BN;
    int mrem = cnt - m0;

    extern __shared__ char smc[];
    uint32_t sb = smem_u32(smc);
    int tid = threadIdx.x;
    int wid = tid >> 5, lane = tid & 31;
    int gp = lane >> 2, tg = lane & 3;
    int wm = (wid & 1) * 64;          // warp M offset (2 warps in M)
    int wn = (wid >> 1) * 64;         // warp N offset (4 warps in N)

    const __half* Ab = A + (size_t)(base + m0) * KTOT;
    const __half* Bb = B + ((size_t)e * n_total + n0) * KTOT;

    // loader: 768 cp16 tasks per stage (A: 256, B: 512), 3 per thread
    auto load_stage = [&](int c, int buf) {
        int k0 = c * BK;
        uint32_t st = sb + buf * STG_B;
        {   // A task: t = tid (0..255): row = t>>1, chunk = t&1
            int r = tid >> 1, ch = tid & 1;
            cp16(st + r * PITCH + ch * 16, Ab + (size_t)r * KTOT + k0 + ch * 8, r < mrem);
        }
        #pragma unroll
        for (int i = 0; i < 2; i++) {   // B tasks: tb = tid + i*256 (0..511)
            int tb = tid + i * 256;
            int r = tb >> 1, ch = tb & 1;
            cp16(st + A_BYTES + r * PITCH + ch * 16, Bb + (size_t)r * KTOT + k0 + ch * 8, true);
        }
    };

    // per-lane ldmatrix offsets (within a stage)
    int m4 = lane >> 3, ri = lane & 7;
    uint32_t a_off[4], b_off[4];
    #pragma unroll
    for (int mi = 0; mi < 4; mi++)
        a_off[mi] = (uint32_t)((wm + mi * 16 + (m4 & 1) * 8 + ri) * PITCH + (m4 >> 1) * 16);
    #pragma unroll
    for (int nj = 0; nj < 4; nj++)
        b_off[nj] = (uint32_t)(A_BYTES + (wn + nj * 16 + (m4 >> 1) * 8 + ri) * PITCH + (m4 & 1) * 16);

    float acc[4][8][4];
    #pragma unroll
    for (int i = 0; i < 4; i++)
        #pragma unroll
        for (int j = 0; j < 8; j++)
            #pragma unroll
            for (int q = 0; q < 4; q++) acc[i][j][q] = 0.f;

    constexpr int NC = KTOT / BK;

    #pragma unroll
    for (int s = 0; s < STAGES - 1; s++) { load_stage(s, s); CP_COMMIT(); }

    #pragma unroll 1
    for (int c = 0; c < NC; c++) {
        CP_WAIT(STAGES - 2);
        __syncthreads();

        if (c + STAGES - 1 < NC) load_stage(c + STAGES - 1, (c + STAGES - 1) % STAGES);
        CP_COMMIT();

        uint32_t st = sb + (c % STAGES) * STG_B;
        uint32_t af[4][4], bf[4][4];
        #pragma unroll
        for (int mi = 0; mi < 4; mi++) ldsm_x4(af[mi], st + a_off[mi]);
        #pragma unroll
        for (int nj = 0; nj < 4; nj++) ldsm_x4(bf[nj], st + b_off[nj]);

        #pragma unroll
        for (int mi = 0; mi < 4; mi++)
            #pragma unroll
            for (int ni = 0; ni < 8; ni++)
                mma_f16(acc[mi][ni], af[mi], &bf[ni >> 1][(ni & 1) * 2]);
    }

    // epilogue: bias (+relu), store (warp covers 64 rows x 64 cols)
    const float* brow = bias + (size_t)e * n_total + n0;
    #pragma unroll
    for (int ni = 0; ni < 8; ni++) {
        int col = wn + ni * 8 + tg * 2;
        float b0 = brow[col], b1 = brow[col + 1];
        #pragma unroll
        for (int mi = 0; mi < 4; mi++) {
            int r0 = wm + mi * 16 + gp;
            float v0 = acc[mi][ni][0] + b0, v1 = acc[mi][ni][1] + b1;
            float v2 = acc[mi][ni][2] + b0, v3 = acc[mi][ni][3] + b1;
            if (RELU) {
                v0 = fmaxf(v0, 0.f); v1 = fmaxf(v1, 0.f);
                v2 = fmaxf(v2, 0.f); v3 = fmaxf(v3, 0.f);
            }
            if (r0 < mrem) {
                OutT* cr = C + (size_t)(base + m0 + r0) * n_total + n0 + col;
                if constexpr (sizeof(OutT) == 2) {
                    *(__half2*)cr = __floats2half2_rn(v0, v1);
                } else { cr[0] = v0; cr[1] = v1; }
            }
            if (r0 + 8 < mrem) {
                OutT* cr = C + (size_t)(base + m0 + r0 + 8) * n_total + n0 + col;
                if constexpr (sizeof(OutT) == 2) {
                    *(__half2*)cr = __floats2half2_rn(v2, v3);
                } else { cr[0] = v2; cr[1] = v3; }
            }
        }
    }
}

// out[t] = w0 * y[slot0] + w1 * y[slot1]
__global__ void k_combine(float* __restrict__ out) {
    int t = blockIdx.x;
    int d4 = threadIdx.x * 4;
    int s0 = g_tok_slot[t * 2 + 0], s1 = g_tok_slot[t * 2 + 1];
    float w0 = g_tok_w[t * 2 + 0],  w1 = g_tok_w[t * 2 + 1];
    float4 y0 = *(const float4*)(g_y + (size_t)s0 * DM + d4);
    float4 y1 = *(const float4*)(g_y + (size_t)s1 * DM + d4);
    float4 r;
    r.x = w0 * y0.x + w1 * y1.x;  r.y = w0 * y0.y + w1 * y1.y;
    r.z = w0 * y0.z + w1 * y1.z;  r.w = w0 * y0.w + w1 * y1.w;
    *(float4*)(out + (size_t)t * DM + d4) = r;
}

// ---------------- launch ----------------
extern "C" void kernel_launch(void* const* d_in, const int* in_sizes, int n_in,
                              void* d_out, int out_size) {
    const float* x  = (const float*)d_in[0];
    const float* gw = (const float*)d_in[1];
    const float* w1 = (const float*)d_in[2];
    const float* b1 = (const float*)d_in[3];
    const float* w2 = (const float*)d_in[4];
    const float* b2 = (const float*)d_in[5];
    float* out = (float*)d_out;

    cudaFuncSetAttribute((const void*)k_gemm<DM, true, __half>,  cudaFuncAttributeMaxDynamicSharedMemorySize, SM_TOTAL);
    cudaFuncSetAttribute((const void*)k_gemm<HID, false, float>, cudaFuncAttributeMaxDynamicSharedMemorySize, SM_TOTAL);

    __half* w1h; cudaGetSymbolAddress((void**)&w1h, g_w1h);
    __half* w2h; cudaGetSymbolAddress((void**)&w2h, g_w2h);
    __half* xgh; cudaGetSymbolAddress((void**)&xgh, g_xgh);
    __half* hh;  cudaGetSymbolAddress((void**)&hh,  g_h);
    float*  yy;  cudaGetSymbolAddress((void**)&yy,  g_y);

    const size_t WN = (size_t)NEXP * HID * DM;
    k_cvt<<<(int)(WN / 8 / 256), 256>>>(w1, w1h);
    k_cvt<<<(int)(WN / 8 / 256), 256>>>(w2, w2h);

    k_zero<<<1, 32>>>();
    k_router<<<NTOK / 8, 256>>>(x, gw);
    k_scan<<<1, 32>>>();
    k_slot<<<NPAIRS / 256, 256>>>();
    k_gather<<<NPAIRS, 256>>>(x);
    // GEMM1: [slots,1024]h x w1h[e][4096,1024]^T -> g_h [slots,4096]h, bias+relu
    k_gemm<DM, true, __half><<<dim3(HID / BN, NPAIRS / BM, NEXP), 256, SM_TOTAL>>>(xgh, w1h, b1, hh, HID);
    // GEMM2: [slots,4096]h x w2h[e][1024,4096]^T -> g_y [slots,1024]f, bias
    k_gemm<HID, false, float><<<dim3(DM / BN, NPAIRS / BM, NEXP), 256, SM_TOTAL>>>(hh, w2h, b2, yy, DM);
    k_combine<<<NTOK, 256>>>(out);
}